// round 1
// baseline (speedup 1.0000x reference)
#include <cuda_runtime.h>
#include <math.h>

// Problem constants (fixed shapes)
#define T_TOK 4096
#define DD    1024
#define HH    2048
#define EE    8
#define CAP   4096      // per-expert token capacity (<= T)
#define NEXP  9         // 8 routed + 1 shared ("expert 8")

typedef unsigned long long ull;

// -------- device scratch (no allocations allowed) --------
__device__ int   g_cnt[EE];
__device__ int   g_tok[EE * CAP];
__device__ float g_wt [EE * CAP];
// SwiGLU intermediate: one row per (expert, slot), 2048 floats each. ~302 MB.
__device__ float g_h[(size_t)NEXP * CAP * HH];

// -------- f32x2 helpers --------
__device__ __forceinline__ ull pack2(float x, float y) {
    ull r; asm("mov.b64 %0, {%1,%2};" : "=l"(r) : "f"(x), "f"(y)); return r;
}
__device__ __forceinline__ void unpack2(ull v, float& lo, float& hi) {
    asm("mov.b64 {%0,%1}, %2;" : "=f"(lo), "=f"(hi) : "l"(v));
}
__device__ __forceinline__ void ffma2(ull& d, ull a, ull b) {
    asm("fma.rn.f32x2 %0, %1, %2, %0;" : "+l"(d) : "l"(a), "l"(b));
}

// -------- kernel 0: zero output + expert counters --------
__global__ void zero_kernel(float4* out4, int n4) {
    int i = blockIdx.x * blockDim.x + threadIdx.x;
    if (i < n4) out4[i] = make_float4(0.f, 0.f, 0.f, 0.f);
    if (blockIdx.x == 0 && threadIdx.x < EE) g_cnt[threadIdx.x] = 0;
}

// -------- kernel 1: router (logits -> top2 -> assignment lists) --------
__global__ void router_kernel(const float* __restrict__ x,
                              const float* __restrict__ wr) {
    int t    = blockIdx.x;            // one token per block
    int w    = threadIdx.x >> 5;      // warp = expert
    int lane = threadIdx.x & 31;
    const float* xr = x + (size_t)t * DD;
    const float* wrow = wr + (size_t)w * DD;
    float s = 0.f;
    for (int d = lane; d < DD; d += 32) s += xr[d] * wrow[d];
    #pragma unroll
    for (int o = 16; o; o >>= 1) s += __shfl_xor_sync(0xffffffffu, s, o);
    __shared__ float lg[EE];
    if (lane == 0) lg[w] = s;
    __syncthreads();
    if (threadIdx.x == 0) {
        int i0 = 0; float m0 = lg[0];
        #pragma unroll
        for (int j = 1; j < EE; ++j) if (lg[j] > m0) { m0 = lg[j]; i0 = j; }
        int i1 = -1; float m1 = -INFINITY;
        #pragma unroll
        for (int j = 0; j < EE; ++j) if (j != i0 && lg[j] > m1) { m1 = lg[j]; i1 = j; }
        // normalized softmax weights over the top-2 (exact):
        float w0 = 1.f / (1.f + expf(m1 - m0));
        float w1 = 1.f - w0;
        int p0 = atomicAdd(&g_cnt[i0], 1);
        g_tok[i0 * CAP + p0] = t; g_wt[i0 * CAP + p0] = w0;
        int p1 = atomicAdd(&g_cnt[i1], 1);
        g_tok[i1 * CAP + p1] = t; g_wt[i1 * CAP + p1] = w1;
    }
}

// =====================================================================
// GEMM1: C[m, c] = x_gathered[m, :] . Brow(c)   (K = 1024)
//   c in [0, 4096): interleaved columns — even c -> Wg row c/2, odd -> Wu row c/2
//   epilogue: h[slot, c/2] = silu(gate) * up
// BM=BN=128, BK=8, 256 threads, 8x8 micro-tile as f32x2 pairs.
// =====================================================================
__global__ void __launch_bounds__(256, 2)
gemm1_kernel(const float* __restrict__ x,
             const float* __restrict__ Wg, const float* __restrict__ Wu,
             const float* __restrict__ sg, const float* __restrict__ su) {
    int e = blockIdx.z;
    int ne = (e == EE) ? T_TOK : g_cnt[e];
    int mbase = blockIdx.y * 128;
    if (mbase >= ne) return;
    int nt = blockIdx.x;              // 0..31

    __shared__ float As[8][128];
    __shared__ float Bs[8][128];

    int tid = threadIdx.x;
    int lr = tid >> 1;                // tile row loaded by this thread
    int lk = (tid & 1) * 4;           // k offset (0 or 4)

    // A row pointer (gathered token)
    int arow = mbase + lr;
    int tokA = 0;
    if (arow < ne) tokA = (e == EE) ? arow : g_tok[e * CAP + arow];
    const float* aptr = x + (size_t)tokA * DD + lk;

    // B row pointer (interleaved gate/up)
    int c = nt * 128 + lr;
    int p = c >> 1;
    const float* brow;
    if (e == EE) brow = ((c & 1) ? su : sg) + (size_t)p * DD;
    else         brow = ((c & 1) ? Wu : Wg) + ((size_t)e * HH + (size_t)p) * DD;
    const float* bptr = brow + lk;

    int tx = tid & 15, ty = tid >> 4;
    int tm = ty * 4;                  // rows tm..tm+3 and tm+64..tm+67
    int tn = tx * 4;                  // cols tn..tn+3 and tn+64..tn+67

    ull acc[8][4];
    #pragma unroll
    for (int r = 0; r < 8; ++r)
        #pragma unroll
        for (int q = 0; q < 4; ++q) acc[r][q] = 0ull;

    float4 aRg = *reinterpret_cast<const float4*>(aptr);
    float4 bRg = *reinterpret_cast<const float4*>(bptr);

    const int KT = DD / 8;            // 128
    for (int kt = 0; kt < KT; ++kt) {
        As[lk + 0][lr] = aRg.x; As[lk + 1][lr] = aRg.y;
        As[lk + 2][lr] = aRg.z; As[lk + 3][lr] = aRg.w;
        Bs[lk + 0][lr] = bRg.x; Bs[lk + 1][lr] = bRg.y;
        Bs[lk + 2][lr] = bRg.z; Bs[lk + 3][lr] = bRg.w;
        __syncthreads();
        if (kt + 1 < KT) {
            aptr += 8; bptr += 8;
            aRg = *reinterpret_cast<const float4*>(aptr);
            bRg = *reinterpret_cast<const float4*>(bptr);
        }
        #pragma unroll
        for (int k = 0; k < 8; ++k) {
            float4 aLo = *reinterpret_cast<const float4*>(&As[k][tm]);
            float4 aHi = *reinterpret_cast<const float4*>(&As[k][tm + 64]);
            ulonglong2 bLo = *reinterpret_cast<const ulonglong2*>(&Bs[k][tn]);
            ulonglong2 bHi = *reinterpret_cast<const ulonglong2*>(&Bs[k][tn + 64]);
            ull a2[8];
            a2[0] = pack2(aLo.x, aLo.x); a2[1] = pack2(aLo.y, aLo.y);
            a2[2] = pack2(aLo.z, aLo.z); a2[3] = pack2(aLo.w, aLo.w);
            a2[4] = pack2(aHi.x, aHi.x); a2[5] = pack2(aHi.y, aHi.y);
            a2[6] = pack2(aHi.z, aHi.z); a2[7] = pack2(aHi.w, aHi.w);
            ull bb0 = bLo.x, bb1 = bLo.y, bb2 = bHi.x, bb3 = bHi.y;
            #pragma unroll
            for (int r = 0; r < 8; ++r) {
                ffma2(acc[r][0], a2[r], bb0);
                ffma2(acc[r][1], a2[r], bb1);
                ffma2(acc[r][2], a2[r], bb2);
                ffma2(acc[r][3], a2[r], bb3);
            }
        }
        __syncthreads();
    }

    // epilogue: SwiGLU -> h
    int colbase = nt * 128;
    #pragma unroll
    for (int j = 0; j < 8; ++j) {
        int rl = (j < 4) ? (tm + j) : (tm + 64 + j - 4);
        int i = mbase + rl;
        if (i >= ne) continue;
        size_t hrow = ((size_t)e * CAP + (size_t)i) * (size_t)HH;
        #pragma unroll
        for (int q = 0; q < 4; ++q) {
            int cg = colbase + ((q < 2) ? (tn + 2 * q) : (tn + 64 + 2 * (q - 2)));
            float gv, uv;
            unpack2(acc[j][q], gv, uv);            // lo = even col = gate
            float s = gv / (1.0f + expf(-gv));
            g_h[hrow + (size_t)(cg >> 1)] = s * uv;
        }
    }
}

// =====================================================================
// GEMM2: out[tok, d] += wt * ( h[slot, :] . Wd_e[d, :] )   (K = 2048, N = 1024)
// =====================================================================
__global__ void __launch_bounds__(256, 2)
gemm2_kernel(const float* __restrict__ Wd, const float* __restrict__ sd,
             float* __restrict__ out) {
    int e = blockIdx.z;
    int ne = (e == EE) ? T_TOK : g_cnt[e];
    int mbase = blockIdx.y * 128;
    if (mbase >= ne) return;
    int nt = blockIdx.x;              // 0..7

    __shared__ float As[8][128];
    __shared__ float Bs[8][128];

    int tid = threadIdx.x;
    int lr = tid >> 1;
    int lk = (tid & 1) * 4;

    // A = h rows (contiguous in slot space, always in-bounds)
    const float* aptr = g_h + ((size_t)e * CAP + (size_t)(mbase + lr)) * (size_t)HH + lk;

    // B row = output dim j
    int j = nt * 128 + lr;
    const float* brow = (e == EE) ? (sd + (size_t)j * HH)
                                  : (Wd + ((size_t)e * DD + (size_t)j) * HH);
    const float* bptr = brow + lk;

    int tx = tid & 15, ty = tid >> 4;
    int tm = ty * 4;
    int tn = tx * 4;

    ull acc[8][4];
    #pragma unroll
    for (int r = 0; r < 8; ++r)
        #pragma unroll
        for (int q = 0; q < 4; ++q) acc[r][q] = 0ull;

    float4 aRg = *reinterpret_cast<const float4*>(aptr);
    float4 bRg = *reinterpret_cast<const float4*>(bptr);

    const int KT = HH / 8;            // 256
    for (int kt = 0; kt < KT; ++kt) {
        As[lk + 0][lr] = aRg.x; As[lk + 1][lr] = aRg.y;
        As[lk + 2][lr] = aRg.z; As[lk + 3][lr] = aRg.w;
        Bs[lk + 0][lr] = bRg.x; Bs[lk + 1][lr] = bRg.y;
        Bs[lk + 2][lr] = bRg.z; Bs[lk + 3][lr] = bRg.w;
        __syncthreads();
        if (kt + 1 < KT) {
            aptr += 8; bptr += 8;
            aRg = *reinterpret_cast<const float4*>(aptr);
            bRg = *reinterpret_cast<const float4*>(bptr);
        }
        #pragma unroll
        for (int k = 0; k < 8; ++k) {
            float4 aLo = *reinterpret_cast<const float4*>(&As[k][tm]);
            float4 aHi = *reinterpret_cast<const float4*>(&As[k][tm + 64]);
            ulonglong2 bLo = *reinterpret_cast<const ulonglong2*>(&Bs[k][tn]);
            ulonglong2 bHi = *reinterpret_cast<const ulonglong2*>(&Bs[k][tn + 64]);
            ull a2[8];
            a2[0] = pack2(aLo.x, aLo.x); a2[1] = pack2(aLo.y, aLo.y);
            a2[2] = pack2(aLo.z, aLo.z); a2[3] = pack2(aLo.w, aLo.w);
            a2[4] = pack2(aHi.x, aHi.x); a2[5] = pack2(aHi.y, aHi.y);
            a2[6] = pack2(aHi.z, aHi.z); a2[7] = pack2(aHi.w, aHi.w);
            ull bb0 = bLo.x, bb1 = bLo.y, bb2 = bHi.x, bb3 = bHi.y;
            #pragma unroll
            for (int r = 0; r < 8; ++r) {
                ffma2(acc[r][0], a2[r], bb0);
                ffma2(acc[r][1], a2[r], bb1);
                ffma2(acc[r][2], a2[r], bb2);
                ffma2(acc[r][3], a2[r], bb3);
            }
        }
        __syncthreads();
    }

    // epilogue: weighted scatter-add into out
    int colbase = nt * 128;
    #pragma unroll
    for (int jr = 0; jr < 8; ++jr) {
        int rl = (jr < 4) ? (tm + jr) : (tm + 64 + jr - 4);
        int i = mbase + rl;
        if (i >= ne) continue;
        int tok; float wt;
        if (e == EE) { tok = i; wt = 1.0f; }
        else { tok = g_tok[e * CAP + i]; wt = g_wt[e * CAP + i]; }
        float* orow = out + (size_t)tok * DD;
        #pragma unroll
        for (int q = 0; q < 4; ++q) {
            int cg = colbase + ((q < 2) ? (tn + 2 * q) : (tn + 64 + 2 * (q - 2)));
            float v0, v1;
            unpack2(acc[jr][q], v0, v1);
            atomicAdd(orow + cg, wt * v0);
            atomicAdd(orow + cg + 1, wt * v1);
        }
    }
}

// -------- launch --------
extern "C" void kernel_launch(void* const* d_in, const int* in_sizes, int n_in,
                              void* d_out, int out_size) {
    const float* x  = (const float*)d_in[0];
    const float* wr = (const float*)d_in[1];
    const float* Wg = (const float*)d_in[2];
    const float* Wu = (const float*)d_in[3];
    const float* Wd = (const float*)d_in[4];
    const float* sg = (const float*)d_in[5];
    const float* su = (const float*)d_in[6];
    const float* sd = (const float*)d_in[7];
    float* out = (float*)d_out;

    int n4 = out_size / 4;                       // 1,048,576 float4s
    zero_kernel<<<(n4 + 255) / 256, 256>>>((float4*)out, n4);
    router_kernel<<<T_TOK, 256>>>(x, wr);

    dim3 g1(32, 32, NEXP);                       // N/128, maxM/128, experts
    gemm1_kernel<<<g1, 256>>>(x, Wg, Wu, sg, su);

    dim3 g2(8, 32, NEXP);                        // D/128, maxM/128, experts
    gemm2_kernel<<<g2, 256>>>(Wd, sd, out);
}

// round 3
// speedup vs baseline: 1.7950x; 1.7950x over previous
#include <cuda_runtime.h>
#include <cuda_bf16.h>
#include <cstdint>
#include <math.h>

// ---------------- problem constants ----------------
#define T_TOK 4096
#define DD    1024
#define HH    2048
#define EE    8
#define CAP   4096
#define NEXP  9          // 8 routed + shared as "expert 8"

// ---------------- tile config ----------------
#define BM 128
#define BN 128
#define BK 32            // k elems per chunk

// stage layout (bytes): each matrix tile is 128 rows x 32 bf16 = 8192 B
#define S_AHI 0
#define S_ALO 8192
#define S_BHI 16384
#define S_BLO 24576
#define STAGE 32768
#define SMEM_DYN (2 * STAGE)   // 65536

typedef unsigned int u32;
typedef unsigned long long u64;

// ---------------- device scratch ----------------
__device__ int   g_cnt[EE];
__device__ int   g_tok[EE * CAP];
__device__ float g_wt [EE * CAP];
// h stored pre-split: u32 = hi_bf16 | (lo_bf16 << 16)
__device__ u32   g_h[(size_t)NEXP * CAP * HH];

// ---------------- helpers ----------------
__device__ __forceinline__ u32 smem_u32(const void* p) {
    u32 a; asm("{ .reg .u64 t; cvta.to.shared.u64 t, %1; cvt.u32.u64 %0, t; }" : "=r"(a) : "l"(p));
    return a;
}
// split fp32 pair -> hi bf16x2 + lo bf16x2 (elem0 in low half)
__device__ __forceinline__ void cvt2(float v0, float v1, u32& hi, u32& lo) {
    u32 h; asm("cvt.rn.bf16x2.f32 %0, %1, %2;" : "=r"(h) : "f"(v1), "f"(v0));
    float h0 = __uint_as_float(h << 16);
    float h1 = __uint_as_float(h & 0xFFFF0000u);
    float l0 = v0 - h0, l1 = v1 - h1;
    u32 l; asm("cvt.rn.bf16x2.f32 %0, %1, %2;" : "=r"(l) : "f"(l1), "f"(l0));
    hi = h; lo = l;
}
__device__ __forceinline__ void sts8(u32 a, u32 x, u32 y) {
    asm volatile("st.shared.v2.u32 [%0], {%1,%2};" :: "r"(a), "r"(x), "r"(y));
}
__device__ __forceinline__ void ldsm4(u32* r, u32 addr) {
    asm volatile("ldmatrix.sync.aligned.m8n8.x4.shared.b16 {%0,%1,%2,%3}, [%4];"
        : "=r"(r[0]), "=r"(r[1]), "=r"(r[2]), "=r"(r[3]) : "r"(addr));
}
__device__ __forceinline__ void mma16816(float* c, const u32* a, u32 b0, u32 b1) {
    asm volatile("mma.sync.aligned.m16n8k16.row.col.f32.bf16.bf16.f32 "
        "{%0,%1,%2,%3}, {%4,%5,%6,%7}, {%8,%9}, {%0,%1,%2,%3};"
        : "+f"(c[0]), "+f"(c[1]), "+f"(c[2]), "+f"(c[3])
        : "r"(a[0]), "r"(a[1]), "r"(a[2]), "r"(a[3]), "r"(b0), "r"(b1));
}
// swizzle: bits[5:4] ^= bits[8:7] (conflict-free 8-row x 16B ldmatrix phases)
__device__ __forceinline__ u32 SW(u32 o) { return o ^ ((o >> 3) & 0x30); }

// ---------------- kernel 0: zero out + counters ----------------
__global__ void zero_kernel(float4* out4, int n4) {
    int i = blockIdx.x * blockDim.x + threadIdx.x;
    if (i < n4) out4[i] = make_float4(0.f, 0.f, 0.f, 0.f);
    if (blockIdx.x == 0 && threadIdx.x < EE) g_cnt[threadIdx.x] = 0;
}

// ---------------- kernel 1: router ----------------
__global__ void router_kernel(const float* __restrict__ x,
                              const float* __restrict__ wr) {
    int t = blockIdx.x, w = threadIdx.x >> 5, lane = threadIdx.x & 31;
    const float* xr = x + (size_t)t * DD;
    const float* wrow = wr + (size_t)w * DD;
    float s = 0.f;
    for (int d = lane; d < DD; d += 32) s += xr[d] * wrow[d];
    #pragma unroll
    for (int o = 16; o; o >>= 1) s += __shfl_xor_sync(0xffffffffu, s, o);
    __shared__ float lg[EE];
    if (lane == 0) lg[w] = s;
    __syncthreads();
    if (threadIdx.x == 0) {
        int i0 = 0; float m0 = lg[0];
        #pragma unroll
        for (int j = 1; j < EE; ++j) if (lg[j] > m0) { m0 = lg[j]; i0 = j; }
        int i1 = -1; float m1 = -INFINITY;
        #pragma unroll
        for (int j = 0; j < EE; ++j) if (j != i0 && lg[j] > m1) { m1 = lg[j]; i1 = j; }
        float w0 = 1.f / (1.f + expf(m1 - m0));
        float w1 = 1.f - w0;
        int p0 = atomicAdd(&g_cnt[i0], 1);
        g_tok[i0 * CAP + p0] = t; g_wt[i0 * CAP + p0] = w0;
        int p1 = atomicAdd(&g_cnt[i1], 1);
        g_tok[i1 * CAP + p1] = t; g_wt[i1 * CAP + p1] = w1;
    }
}

// =====================================================================
// GEMM1: C[128,128] = Xg[128,K=1024] . W^T  (B rows = interleaved gate/up)
// 3-pass bf16 mma.sync. Epilogue: SwiGLU -> g_h packed (hi|lo).
// =====================================================================
__global__ void __launch_bounds__(256, 1)
gemm1_kernel(const float* __restrict__ x,
             const float* __restrict__ Wg, const float* __restrict__ Wu,
             const float* __restrict__ sg, const float* __restrict__ su) {
    int e = blockIdx.z;
    int ne = (e == EE) ? T_TOK : g_cnt[e];
    int mbase = blockIdx.y * BM;
    if (mbase >= ne) return;
    int ntile = blockIdx.x;

    extern __shared__ char smem[];
    u32 sb = smem_u32(smem);
    __shared__ int s_tok[128];
    int tid = threadIdx.x, wid = tid >> 5, lane = tid & 31;

    if (tid < 128) {
        int r = mbase + tid;
        s_tok[tid] = (e == EE) ? r : ((r < ne) ? g_tok[e * CAP + r] : g_tok[e * CAP]);
    }
    __syncthreads();

    // ---- producer setup: thread -> (row, k-half) ----
    int prow = tid >> 1, phalf = tid & 1;
    const float* aP = x + (size_t)s_tok[prow] * DD + phalf * 16;
    int cg = ntile * BN + prow;
    const float* bP;
    if (e == EE) bP = ((cg & 1) ? su : sg) + (size_t)(cg >> 1) * DD + phalf * 16;
    else         bP = ((cg & 1) ? Wu : Wg) + ((size_t)e * HH + (size_t)(cg >> 1)) * DD + phalf * 16;
    u32 pmask = ((u32)(prow * 64) >> 3) & 0x30;
    u32 pbase = (u32)(prow * 64 + phalf * 32);

    // ---- consumer setup ----
    int wm = wid & 3, wn = wid >> 2;          // warp tile: rows wm*32, cols wn*64
    int lr  = (lane & 7) + ((lane >> 3) & 1) * 8;
    int lkb = (lane >> 4) & 1;
    u32 lmA[2][2], lmB[4][2];
    #pragma unroll
    for (int tm = 0; tm < 2; ++tm)
        #pragma unroll
        for (int ks = 0; ks < 2; ++ks) {
            u32 o = (u32)((wm * 32 + tm * 16 + lr) * 64 + ks * 32 + lkb * 16);
            lmA[tm][ks] = SW(o);
        }
    #pragma unroll
    for (int nb = 0; nb < 4; ++nb)
        #pragma unroll
        for (int ks = 0; ks < 2; ++ks) {
            u32 o = (u32)((wn * 64 + nb * 16 + lr) * 64 + ks * 32 + lkb * 16);
            lmB[nb][ks] = SW(o);
        }

    float acc[2][8][4];
    #pragma unroll
    for (int a = 0; a < 2; ++a)
        #pragma unroll
        for (int b = 0; b < 8; ++b)
            #pragma unroll
            for (int c = 0; c < 4; ++c) acc[a][b][c] = 0.f;

    const int NC = DD / BK;  // 32
    float4 aR[4], bR[4];
    #pragma unroll
    for (int q = 0; q < 4; ++q) { aR[q] = *(const float4*)(aP + q * 4); bR[q] = *(const float4*)(bP + q * 4); }
    // store chunk 0 into stage 0
    {
        u32 base = sb;
        #pragma unroll
        for (int q = 0; q < 4; ++q) {
            u32 h0, l0, h1, l1, adr = ((pbase + q * 8) ^ pmask);
            cvt2(aR[q].x, aR[q].y, h0, l0); cvt2(aR[q].z, aR[q].w, h1, l1);
            sts8(base + S_AHI + adr, h0, h1); sts8(base + S_ALO + adr, l0, l1);
            cvt2(bR[q].x, bR[q].y, h0, l0); cvt2(bR[q].z, bR[q].w, h1, l1);
            sts8(base + S_BHI + adr, h0, h1); sts8(base + S_BLO + adr, l0, l1);
        }
    }
    __syncthreads();

    for (int kt = 0; kt < NC; ++kt) {
        u32 cur = sb + (u32)(kt & 1) * STAGE;
        if (kt + 1 < NC) {
            const float* a2 = aP + (kt + 1) * BK;
            const float* b2 = bP + (kt + 1) * BK;
            #pragma unroll
            for (int q = 0; q < 4; ++q) { aR[q] = *(const float4*)(a2 + q * 4); bR[q] = *(const float4*)(b2 + q * 4); }
        }
        #pragma unroll
        for (int ks = 0; ks < 2; ++ks) {
            u32 ah[2][4], al[2][4], bh[4][4], bl[4][4];
            #pragma unroll
            for (int tm = 0; tm < 2; ++tm) {
                ldsm4(ah[tm], cur + S_AHI + lmA[tm][ks]);
                ldsm4(al[tm], cur + S_ALO + lmA[tm][ks]);
            }
            #pragma unroll
            for (int nb = 0; nb < 4; ++nb) {
                ldsm4(bh[nb], cur + S_BHI + lmB[nb][ks]);
                ldsm4(bl[nb], cur + S_BLO + lmB[nb][ks]);
            }
            #pragma unroll
            for (int mt = 0; mt < 2; ++mt)
                #pragma unroll
                for (int nb = 0; nb < 4; ++nb) {
                    mma16816(acc[mt][nb * 2],     ah[mt], bh[nb][0], bh[nb][2]);
                    mma16816(acc[mt][nb * 2 + 1], ah[mt], bh[nb][1], bh[nb][3]);
                }
            #pragma unroll
            for (int mt = 0; mt < 2; ++mt)
                #pragma unroll
                for (int nb = 0; nb < 4; ++nb) {
                    mma16816(acc[mt][nb * 2],     ah[mt], bl[nb][0], bl[nb][2]);
                    mma16816(acc[mt][nb * 2 + 1], ah[mt], bl[nb][1], bl[nb][3]);
                }
            #pragma unroll
            for (int mt = 0; mt < 2; ++mt)
                #pragma unroll
                for (int nb = 0; nb < 4; ++nb) {
                    mma16816(acc[mt][nb * 2],     al[mt], bh[nb][0], bh[nb][2]);
                    mma16816(acc[mt][nb * 2 + 1], al[mt], bh[nb][1], bh[nb][3]);
                }
        }
        if (kt + 1 < NC) {
            u32 nxt = sb + (u32)((kt + 1) & 1) * STAGE;
            #pragma unroll
            for (int q = 0; q < 4; ++q) {
                u32 h0, l0, h1, l1, adr = ((pbase + q * 8) ^ pmask);
                cvt2(aR[q].x, aR[q].y, h0, l0); cvt2(aR[q].z, aR[q].w, h1, l1);
                sts8(nxt + S_AHI + adr, h0, h1); sts8(nxt + S_ALO + adr, l0, l1);
                cvt2(bR[q].x, bR[q].y, h0, l0); cvt2(bR[q].z, bR[q].w, h1, l1);
                sts8(nxt + S_BHI + adr, h0, h1); sts8(nxt + S_BLO + adr, l0, l1);
            }
        }
        __syncthreads();
    }

    // ---- epilogue: SwiGLU, split to (hi|lo), write g_h ----
    size_t slotBase = (size_t)e * CAP + mbase;
    int rbase = wm * 32 + (lane >> 2);
    int cquad = lane & 3;
    #pragma unroll
    for (int mt = 0; mt < 2; ++mt)
        #pragma unroll
        for (int nt = 0; nt < 8; ++nt) {
            int hcol = ntile * 64 + wn * 32 + nt * 4 + cquad;
            float* c = acc[mt][nt];
            int r0 = rbase + mt * 16;
            #pragma unroll
            for (int half = 0; half < 2; ++half) {
                float gv = c[half * 2], uv = c[half * 2 + 1];
                float h = (gv / (1.f + __expf(-gv))) * uv;
                __nv_bfloat16 hb = __float2bfloat16(h);
                float hf = __bfloat162float(hb);
                __nv_bfloat16 lb = __float2bfloat16(h - hf);
                u32 packed = (u32)__bfloat16_as_ushort(hb) |
                             ((u32)__bfloat16_as_ushort(lb) << 16);
                g_h[(slotBase + (size_t)(r0 + half * 8)) * HH + (size_t)hcol] = packed;
            }
        }
}

// =====================================================================
// GEMM2: C[128,128] = h[128,K=2048] . Wd^T, weighted atomic scatter to out
// =====================================================================
__global__ void __launch_bounds__(256, 1)
gemm2_kernel(const float* __restrict__ Wd, const float* __restrict__ sd,
             float* __restrict__ out) {
    int e = blockIdx.z;
    int ne = (e == EE) ? T_TOK : g_cnt[e];
    int mbase = blockIdx.y * BM;
    if (mbase >= ne) return;
    int ntile = blockIdx.x;

    extern __shared__ char smem[];
    u32 sb = smem_u32(smem);
    __shared__ int   s_tok[128];
    __shared__ float s_wt[128];
    int tid = threadIdx.x, wid = tid >> 5, lane = tid & 31;

    if (tid < 128) {
        int r = mbase + tid;
        if (e == EE)     { s_tok[tid] = r; s_wt[tid] = 1.f; }
        else if (r < ne) { s_tok[tid] = g_tok[e * CAP + r]; s_wt[tid] = g_wt[e * CAP + r]; }
        else             { s_tok[tid] = 0; s_wt[tid] = 0.f; }
    }
    __syncthreads();

    size_t slotBase = (size_t)e * CAP + mbase;

    int prow = tid >> 1, phalf = tid & 1;
    const u32* aP = g_h + (slotBase + (size_t)prow) * HH + phalf * 16;
    int brow = ntile * BN + prow;
    const float* bP = (e == EE) ? (sd + (size_t)brow * HH)
                                : (Wd + ((size_t)e * DD + (size_t)brow) * HH);
    bP += phalf * 16;
    u32 pmask = ((u32)(prow * 64) >> 3) & 0x30;
    u32 pbase = (u32)(prow * 64 + phalf * 32);

    int wm = wid & 3, wn = wid >> 2;
    int lr  = (lane & 7) + ((lane >> 3) & 1) * 8;
    int lkb = (lane >> 4) & 1;
    u32 lmA[2][2], lmB[4][2];
    #pragma unroll
    for (int tm = 0; tm < 2; ++tm)
        #pragma unroll
        for (int ks = 0; ks < 2; ++ks) {
            u32 o = (u32)((wm * 32 + tm * 16 + lr) * 64 + ks * 32 + lkb * 16);
            lmA[tm][ks] = SW(o);
        }
    #pragma unroll
    for (int nb = 0; nb < 4; ++nb)
        #pragma unroll
        for (int ks = 0; ks < 2; ++ks) {
            u32 o = (u32)((wn * 64 + nb * 16 + lr) * 64 + ks * 32 + lkb * 16);
            lmB[nb][ks] = SW(o);
        }

    float acc[2][8][4];
    #pragma unroll
    for (int a = 0; a < 2; ++a)
        #pragma unroll
        for (int b = 0; b < 8; ++b)
            #pragma unroll
            for (int c = 0; c < 4; ++c) acc[a][b][c] = 0.f;

    const int NC = HH / BK;  // 64
    uint4  aR[4]; float4 bR[4];
    #pragma unroll
    for (int q = 0; q < 4; ++q) { aR[q] = *(const uint4*)(aP + q * 4); bR[q] = *(const float4*)(bP + q * 4); }
    {
        u32 base = sb;
        #pragma unroll
        for (int q = 0; q < 4; ++q) {
            u32 adr = ((pbase + q * 8) ^ pmask);
            u32 h0 = __byte_perm(aR[q].x, aR[q].y, 0x5410);
            u32 h1 = __byte_perm(aR[q].z, aR[q].w, 0x5410);
            u32 l0 = __byte_perm(aR[q].x, aR[q].y, 0x7632);
            u32 l1 = __byte_perm(aR[q].z, aR[q].w, 0x7632);
            sts8(base + S_AHI + adr, h0, h1); sts8(base + S_ALO + adr, l0, l1);
            u32 bh0, bl0, bh1, bl1;
            cvt2(bR[q].x, bR[q].y, bh0, bl0); cvt2(bR[q].z, bR[q].w, bh1, bl1);
            sts8(base + S_BHI + adr, bh0, bh1); sts8(base + S_BLO + adr, bl0, bl1);
        }
    }
    __syncthreads();

    for (int kt = 0; kt < NC; ++kt) {
        u32 cur = sb + (u32)(kt & 1) * STAGE;
        if (kt + 1 < NC) {
            const u32*   a2 = aP + (kt + 1) * BK;
            const float* b2 = bP + (kt + 1) * BK;
            #pragma unroll
            for (int q = 0; q < 4; ++q) { aR[q] = *(const uint4*)(a2 + q * 4); bR[q] = *(const float4*)(b2 + q * 4); }
        }
        #pragma unroll
        for (int ks = 0; ks < 2; ++ks) {
            u32 ah[2][4], al[2][4], bh[4][4], bl[4][4];
            #pragma unroll
            for (int tm = 0; tm < 2; ++tm) {
                ldsm4(ah[tm], cur + S_AHI + lmA[tm][ks]);
                ldsm4(al[tm], cur + S_ALO + lmA[tm][ks]);
            }
            #pragma unroll
            for (int nb = 0; nb < 4; ++nb) {
                ldsm4(bh[nb], cur + S_BHI + lmB[nb][ks]);
                ldsm4(bl[nb], cur + S_BLO + lmB[nb][ks]);
            }
            #pragma unroll
            for (int mt = 0; mt < 2; ++mt)
                #pragma unroll
                for (int nb = 0; nb < 4; ++nb) {
                    mma16816(acc[mt][nb * 2],     ah[mt], bh[nb][0], bh[nb][2]);
                    mma16816(acc[mt][nb * 2 + 1], ah[mt], bh[nb][1], bh[nb][3]);
                }
            #pragma unroll
            for (int mt = 0; mt < 2; ++mt)
                #pragma unroll
                for (int nb = 0; nb < 4; ++nb) {
                    mma16816(acc[mt][nb * 2],     ah[mt], bl[nb][0], bl[nb][2]);
                    mma16816(acc[mt][nb * 2 + 1], ah[mt], bl[nb][1], bl[nb][3]);
                }
            #pragma unroll
            for (int mt = 0; mt < 2; ++mt)
                #pragma unroll
                for (int nb = 0; nb < 4; ++nb) {
                    mma16816(acc[mt][nb * 2],     al[mt], bh[nb][0], bh[nb][2]);
                    mma16816(acc[mt][nb * 2 + 1], al[mt], bh[nb][1], bh[nb][3]);
                }
        }
        if (kt + 1 < NC) {
            u32 nxt = sb + (u32)((kt + 1) & 1) * STAGE;
            #pragma unroll
            for (int q = 0; q < 4; ++q) {
                u32 adr = ((pbase + q * 8) ^ pmask);
                u32 h0 = __byte_perm(aR[q].x, aR[q].y, 0x5410);
                u32 h1 = __byte_perm(aR[q].z, aR[q].w, 0x5410);
                u32 l0 = __byte_perm(aR[q].x, aR[q].y, 0x7632);
                u32 l1 = __byte_perm(aR[q].z, aR[q].w, 0x7632);
                sts8(nxt + S_AHI + adr, h0, h1); sts8(nxt + S_ALO + adr, l0, l1);
                u32 bh0, bl0, bh1, bl1;
                cvt2(bR[q].x, bR[q].y, bh0, bl0); cvt2(bR[q].z, bR[q].w, bh1, bl1);
                sts8(nxt + S_BHI + adr, bh0, bh1); sts8(nxt + S_BLO + adr, bl0, bl1);
            }
        }
        __syncthreads();
    }

    // ---- epilogue: weighted atomic scatter ----
    int nv = ne - mbase; if (nv > BM) nv = BM;
    int rbase = wm * 32 + (lane >> 2);
    int cquad = lane & 3;
    #pragma unroll
    for (int mt = 0; mt < 2; ++mt)
        #pragma unroll
        for (int nt = 0; nt < 8; ++nt) {
            int col = ntile * BN + wn * 64 + nt * 8 + cquad * 2;
            float* c = acc[mt][nt];
            #pragma unroll
            for (int half = 0; half < 2; ++half) {
                int r = rbase + mt * 16 + half * 8;
                if (r < nv) {
                    int tok = s_tok[r]; float wt = s_wt[r];
                    float* orow = out + (size_t)tok * DD + col;
                    atomicAdd(orow,     wt * c[half * 2]);
                    atomicAdd(orow + 1, wt * c[half * 2 + 1]);
                }
            }
        }
}

// ---------------- launch ----------------
extern "C" void kernel_launch(void* const* d_in, const int* in_sizes, int n_in,
                              void* d_out, int out_size) {
    const float* x  = (const float*)d_in[0];
    const float* wr = (const float*)d_in[1];
    const float* Wg = (const float*)d_in[2];
    const float* Wu = (const float*)d_in[3];
    const float* Wd = (const float*)d_in[4];
    const float* sg = (const float*)d_in[5];
    const float* su = (const float*)d_in[6];
    const float* sd = (const float*)d_in[7];
    float* out = (float*)d_out;

    static int attr_done = 0;
    if (!attr_done) {
        cudaFuncSetAttribute(gemm1_kernel, cudaFuncAttributeMaxDynamicSharedMemorySize, SMEM_DYN);
        cudaFuncSetAttribute(gemm2_kernel, cudaFuncAttributeMaxDynamicSharedMemorySize, SMEM_DYN);
        attr_done = 1;
    }

    int n4 = out_size / 4;
    zero_kernel<<<(n4 + 255) / 256, 256>>>((float4*)out, n4);
    router_kernel<<<T_TOK, 256>>>(x, wr);

    dim3 g1(32, 32, NEXP);   // N-tiles(4096/128), M-tiles(max 4096/128), experts
    gemm1_kernel<<<g1, 256, SMEM_DYN>>>(x, Wg, Wu, sg, su);

    dim3 g2(8, 32, NEXP);    // N-tiles(1024/128)
    gemm2_kernel<<<g2, 256, SMEM_DYN>>>(Wd, sd, out);
}

// round 4
// speedup vs baseline: 3.0737x; 1.7123x over previous
#include <cuda_runtime.h>
#include <cuda_fp16.h>
#include <cstdint>
#include <math.h>

// ---------------- problem constants ----------------
#define T_TOK 4096
#define DD    1024
#define HH    2048
#define EE    8
#define CAP   4096
#define NEXP  9          // 8 routed + shared as "expert 8"

// ---------------- tile config ----------------
#define BM 128
#define BN 128
#define BK 32            // k elems (fp16) per chunk
#define NSTAGE 4
// per-stage: Ahi 8KB | Alo 8KB | Bh 8KB
#define S_A  0
#define S_AL 8192
#define S_B  16384
#define STG  24576
#define SMEM_DYN (NSTAGE * STG)   // 98304

typedef unsigned int u32;
typedef unsigned long long u64;

// ---------------- device scratch (zero-init globals; no allocs) ----------------
__device__ int   g_cnt[EE];
__device__ int   g_tok[EE * CAP];
__device__ float g_wt [EE * CAP];
__device__ __half g_xhi[(size_t)T_TOK * DD];
__device__ __half g_xlo[(size_t)T_TOK * DD];
__device__ __half g_wgu[(size_t)NEXP * 4096 * DD];   // interleaved gate/up rows
__device__ __half g_wd [(size_t)NEXP * DD * HH];
__device__ __half g_hhi[(size_t)NEXP * CAP * HH];
__device__ __half g_hlo[(size_t)NEXP * CAP * HH];

// ---------------- helpers ----------------
__device__ __forceinline__ u32 smem_u32(const void* p) {
    u32 a; asm("{ .reg .u64 t; cvta.to.shared.u64 t, %1; cvt.u32.u64 %0, t; }" : "=r"(a) : "l"(p));
    return a;
}
__device__ __forceinline__ void cpa16(u32 dst, const void* gsrc) {
    asm volatile("cp.async.cg.shared.global [%0], [%1], 16;" :: "r"(dst), "l"(gsrc) : "memory");
}
#define CP_COMMIT() asm volatile("cp.async.commit_group;" ::: "memory")
#define CP_WAIT(n)  asm volatile("cp.async.wait_group %0;" :: "n"(n) : "memory")

__device__ __forceinline__ void ldsm4(u32* r, u32 addr) {
    asm volatile("ldmatrix.sync.aligned.m8n8.x4.shared.b16 {%0,%1,%2,%3}, [%4];"
        : "=r"(r[0]), "=r"(r[1]), "=r"(r[2]), "=r"(r[3]) : "r"(addr));
}
__device__ __forceinline__ void mma16816(float* c, const u32* a, u32 b0, u32 b1) {
    asm volatile("mma.sync.aligned.m16n8k16.row.col.f32.f16.f16.f32 "
        "{%0,%1,%2,%3}, {%4,%5,%6,%7}, {%8,%9}, {%0,%1,%2,%3};"
        : "+f"(c[0]), "+f"(c[1]), "+f"(c[2]), "+f"(c[3])
        : "r"(a[0]), "r"(a[1]), "r"(a[2]), "r"(a[3]), "r"(b0), "r"(b1));
}
// swizzle: bits[5:4] ^= bits[8:7] (conflict-free for 64B-row tiles; proven R3)
__device__ __forceinline__ u32 SW(u32 o) { return o ^ ((o >> 3) & 0x30); }

__device__ __forceinline__ uint2 pack_hi(float4 v) {
    __half2 h0 = __floats2half2_rn(v.x, v.y);
    __half2 h1 = __floats2half2_rn(v.z, v.w);
    uint2 r; r.x = *(u32*)&h0; r.y = *(u32*)&h1; return r;
}
__device__ __forceinline__ void pack_hilo(float4 v, uint2& hi, uint2& lo) {
    __half2 h0 = __floats2half2_rn(v.x, v.y);
    __half2 h1 = __floats2half2_rn(v.z, v.w);
    float2 f0 = __half22float2(h0), f1 = __half22float2(h1);
    __half2 l0 = __floats2half2_rn(v.x - f0.x, v.y - f0.y);
    __half2 l1 = __floats2half2_rn(v.z - f1.x, v.w - f1.y);
    hi.x = *(u32*)&h0; hi.y = *(u32*)&h1;
    lo.x = *(u32*)&l0; lo.y = *(u32*)&l1;
}

// ---------------- kernel 0: zero output + counters ----------------
__global__ void zero_kernel(float4* out4, int n4) {
    int i = blockIdx.x * blockDim.x + threadIdx.x;
    if (i < n4) out4[i] = make_float4(0.f, 0.f, 0.f, 0.f);
    if (blockIdx.x == 0 && threadIdx.x < EE) g_cnt[threadIdx.x] = 0;
}

// ---------------- conversion kernels (once per launch) ----------------
__global__ void conv_x_kernel(const float* __restrict__ x) {
    int t = blockIdx.x, c = threadIdx.x;               // 256 thr, D/4 = 256
    float4 v = ((const float4*)(x + (size_t)t * DD))[c];
    uint2 hi, lo; pack_hilo(v, hi, lo);
    size_t o = (size_t)t * (DD / 4) + c;
    ((uint2*)g_xhi)[o] = hi;
    ((uint2*)g_xlo)[o] = lo;
}
__global__ void conv_wgu_kernel(const float* __restrict__ Wg, const float* __restrict__ Wu,
                                const float* __restrict__ sg, const float* __restrict__ su) {
    int b = blockIdx.x;                                 // row in [0, NEXP*4096)
    int e = b >> 12, r = b & 4095;
    const float* src;
    if (e < EE) src = ((r & 1) ? Wu : Wg) + ((size_t)e * HH + (size_t)(r >> 1)) * DD;
    else        src = ((r & 1) ? su : sg) + (size_t)(r >> 1) * DD;
    float4 v = ((const float4*)src)[threadIdx.x];
    ((uint2*)g_wgu)[(size_t)b * 256 + threadIdx.x] = pack_hi(v);
}
__global__ void conv_wd_kernel(const float* __restrict__ Wd, const float* __restrict__ sd) {
    int b = blockIdx.x;                                 // row in [0, NEXP*DD), 512 thr
    int e = b >> 10, d = b & 1023;
    const float* src = (e < EE) ? Wd + ((size_t)e * DD + (size_t)d) * HH
                                : sd + (size_t)d * HH;
    float4 v = ((const float4*)src)[threadIdx.x];
    ((uint2*)g_wd)[(size_t)b * 512 + threadIdx.x] = pack_hi(v);
}

// ---------------- router ----------------
__global__ void router_kernel(const float* __restrict__ x,
                              const float* __restrict__ wr) {
    int t = blockIdx.x, w = threadIdx.x >> 5, lane = threadIdx.x & 31;
    const float* xr = x + (size_t)t * DD;
    const float* wrow = wr + (size_t)w * DD;
    float s = 0.f;
    for (int d = lane; d < DD; d += 32) s += xr[d] * wrow[d];
    #pragma unroll
    for (int o = 16; o; o >>= 1) s += __shfl_xor_sync(0xffffffffu, s, o);
    __shared__ float lg[EE];
    if (lane == 0) lg[w] = s;
    __syncthreads();
    if (threadIdx.x == 0) {
        int i0 = 0; float m0 = lg[0];
        #pragma unroll
        for (int j = 1; j < EE; ++j) if (lg[j] > m0) { m0 = lg[j]; i0 = j; }
        int i1 = -1; float m1 = -INFINITY;
        #pragma unroll
        for (int j = 0; j < EE; ++j) if (j != i0 && lg[j] > m1) { m1 = lg[j]; i1 = j; }
        float w0 = 1.f / (1.f + expf(m1 - m0));
        float w1 = 1.f - w0;
        int p0 = atomicAdd(&g_cnt[i0], 1);
        g_tok[i0 * CAP + p0] = t; g_wt[i0 * CAP + p0] = w0;
        int p1 = atomicAdd(&g_cnt[i1], 1);
        g_tok[i1 * CAP + p1] = t; g_wt[i1 * CAP + p1] = w1;
    }
}

// common macros for the GEMM mainloop
#define ISSUE6(s, PA, PAL, PB) do { \
    u32 _st = sb + (u32)((s) & (NSTAGE - 1)) * STG; \
    size_t _ko = (size_t)(s) * BK; \
    cpa16(_st + S_A  + d0, (PA)  + offA0 + _ko); \
    cpa16(_st + S_A  + d1, (PA)  + offA1 + _ko); \
    cpa16(_st + S_AL + d0, (PAL) + offA0 + _ko); \
    cpa16(_st + S_AL + d1, (PAL) + offA1 + _ko); \
    cpa16(_st + S_B  + d0, (PB)  + offB0 + _ko); \
    cpa16(_st + S_B  + d1, (PB)  + offB1 + _ko); \
} while (0)

#define CONSUME_CHUNK(cur) \
    _Pragma("unroll") \
    for (int ks = 0; ks < 2; ++ks) { \
        u32 ah[2][4], al[2][4], bh[4][4]; \
        _Pragma("unroll") \
        for (int tm = 0; tm < 2; ++tm) { \
            ldsm4(ah[tm], (cur) + S_A  + lmA[tm][ks]); \
            ldsm4(al[tm], (cur) + S_AL + lmA[tm][ks]); \
        } \
        _Pragma("unroll") \
        for (int nb = 0; nb < 4; ++nb) ldsm4(bh[nb], (cur) + S_B + lmB[nb][ks]); \
        _Pragma("unroll") \
        for (int mt = 0; mt < 2; ++mt) \
            _Pragma("unroll") \
            for (int nb = 0; nb < 4; ++nb) { \
                mma16816(acc[mt][nb * 2],     ah[mt], bh[nb][0], bh[nb][2]); \
                mma16816(acc[mt][nb * 2 + 1], ah[mt], bh[nb][1], bh[nb][3]); \
            } \
        _Pragma("unroll") \
        for (int mt = 0; mt < 2; ++mt) \
            _Pragma("unroll") \
            for (int nb = 0; nb < 4; ++nb) { \
                mma16816(acc[mt][nb * 2],     al[mt], bh[nb][0], bh[nb][2]); \
                mma16816(acc[mt][nb * 2 + 1], al[mt], bh[nb][1], bh[nb][3]); \
            } \
    }

#define FRAG_SETUP() \
    int wm = wid & 3, wn = wid >> 2; \
    int lr = lane & 15, lkb = lane >> 4; \
    u32 lmA[2][2], lmB[4][2]; \
    _Pragma("unroll") \
    for (int tm = 0; tm < 2; ++tm) \
        _Pragma("unroll") \
        for (int ks = 0; ks < 2; ++ks) \
            lmA[tm][ks] = SW((u32)((wm * 32 + tm * 16 + lr) * 64 + ks * 32 + lkb * 16)); \
    _Pragma("unroll") \
    for (int nb = 0; nb < 4; ++nb) \
        _Pragma("unroll") \
        for (int ks = 0; ks < 2; ++ks) \
            lmB[nb][ks] = SW((u32)((wn * 64 + nb * 16 + lr) * 64 + ks * 32 + lkb * 16)); \
    float acc[2][8][4]; \
    _Pragma("unroll") \
    for (int a_ = 0; a_ < 2; ++a_) \
        _Pragma("unroll") \
        for (int b_ = 0; b_ < 8; ++b_) \
            _Pragma("unroll") \
            for (int c_ = 0; c_ < 4; ++c_) acc[a_][b_][c_] = 0.f;

// =====================================================================
// GEMM1: C[128,128] = Xg[128,1024] . Wgu^T ; epilogue SwiGLU -> h planes
// =====================================================================
__global__ void __launch_bounds__(256, 2)
gemm1_kernel() {
    int e = blockIdx.z;
    int ne = (e == EE) ? T_TOK : g_cnt[e];
    int mbase = blockIdx.y * BM;
    if (mbase >= ne) return;
    int ntile = blockIdx.x;

    extern __shared__ char smem[];
    u32 sb = smem_u32(smem);
    __shared__ int s_tok[128];
    int tid = threadIdx.x, wid = tid >> 5, lane = tid & 31;
    if (tid < 128) {
        int r = mbase + tid;
        s_tok[tid] = (e == EE) ? r : ((r < ne) ? g_tok[e * CAP + r] : g_tok[e * CAP]);
    }
    __syncthreads();

    // producer mapping: thread -> rows (prow, prow+64), 16B quarter q
    int prow = tid >> 2, q = tid & 3;
    size_t offA0 = (size_t)s_tok[prow] * DD + q * 8;
    size_t offA1 = (size_t)s_tok[prow + 64] * DD + q * 8;
    size_t bb = (size_t)(e * 4096 + ntile * 128);
    size_t offB0 = (bb + prow) * DD + q * 8;
    size_t offB1 = (bb + prow + 64) * DD + q * 8;
    u32 d0 = SW((u32)(prow * 64 + q * 16));
    u32 d1 = SW((u32)((prow + 64) * 64 + q * 16));

    FRAG_SETUP();

    const int NC = DD / BK;  // 32
    #pragma unroll
    for (int s = 0; s < NSTAGE - 1; ++s) { ISSUE6(s, g_xhi, g_xlo, g_wgu); CP_COMMIT(); }

    for (int kt = 0; kt < NC; ++kt) {
        CP_WAIT(NSTAGE - 2);
        __syncthreads();
        if (kt + NSTAGE - 1 < NC) ISSUE6(kt + NSTAGE - 1, g_xhi, g_xlo, g_wgu);
        CP_COMMIT();
        u32 cur = sb + (u32)(kt & (NSTAGE - 1)) * STG;
        CONSUME_CHUNK(cur);
    }

    // epilogue: SwiGLU -> fp16 hi/lo planes
    size_t slotBase = (size_t)e * CAP + mbase;
    int rbase = wm * 32 + (lane >> 2), cquad = lane & 3;
    #pragma unroll
    for (int mt = 0; mt < 2; ++mt)
        #pragma unroll
        for (int nt = 0; nt < 8; ++nt) {
            int hcol = ntile * 64 + wn * 32 + nt * 4 + cquad;
            float* c = acc[mt][nt];
            #pragma unroll
            for (int half = 0; half < 2; ++half) {
                int r = rbase + mt * 16 + half * 8;
                float gv = c[half * 2], uv = c[half * 2 + 1];
                float h = (gv / (1.f + __expf(-gv))) * uv;
                __half hb = __float2half_rn(h);
                __half lb = __float2half_rn(h - __half2float(hb));
                size_t o = (slotBase + (size_t)r) * HH + (size_t)hcol;
                g_hhi[o] = hb;
                g_hlo[o] = lb;
            }
        }
}

// =====================================================================
// GEMM2: C[128,128] = h[128,2048] . Wd^T ; weighted atomic scatter
// =====================================================================
__global__ void __launch_bounds__(256, 2)
gemm2_kernel(float* __restrict__ out) {
    int e = blockIdx.z;
    int ne = (e == EE) ? T_TOK : g_cnt[e];
    int mbase = blockIdx.y * BM;
    if (mbase >= ne) return;
    int ntile = blockIdx.x;

    extern __shared__ char smem[];
    u32 sb = smem_u32(smem);
    __shared__ int   s_tok[128];
    __shared__ float s_wt[128];
    int tid = threadIdx.x, wid = tid >> 5, lane = tid & 31;
    if (tid < 128) {
        int r = mbase + tid;
        if (e == EE)     { s_tok[tid] = r; s_wt[tid] = 1.f; }
        else if (r < ne) { s_tok[tid] = g_tok[e * CAP + r]; s_wt[tid] = g_wt[e * CAP + r]; }
        else             { s_tok[tid] = 0; s_wt[tid] = 0.f; }
    }
    __syncthreads();

    size_t slotBase = (size_t)e * CAP + mbase;
    int prow = tid >> 2, q = tid & 3;
    size_t offA0 = (slotBase + (size_t)prow) * HH + q * 8;
    size_t offA1 = (slotBase + (size_t)(prow + 64)) * HH + q * 8;
    size_t wb = (size_t)(e * DD + ntile * 128);
    size_t offB0 = (wb + prow) * HH + q * 8;
    size_t offB1 = (wb + prow + 64) * HH + q * 8;
    u32 d0 = SW((u32)(prow * 64 + q * 16));
    u32 d1 = SW((u32)((prow + 64) * 64 + q * 16));

    FRAG_SETUP();

    const int NC = HH / BK;  // 64
    #pragma unroll
    for (int s = 0; s < NSTAGE - 1; ++s) { ISSUE6(s, g_hhi, g_hlo, g_wd); CP_COMMIT(); }

    for (int kt = 0; kt < NC; ++kt) {
        CP_WAIT(NSTAGE - 2);
        __syncthreads();
        if (kt + NSTAGE - 1 < NC) ISSUE6(kt + NSTAGE - 1, g_hhi, g_hlo, g_wd);
        CP_COMMIT();
        u32 cur = sb + (u32)(kt & (NSTAGE - 1)) * STG;
        CONSUME_CHUNK(cur);
    }

    // epilogue: weighted atomic scatter
    int nv = ne - mbase; if (nv > BM) nv = BM;
    int rbase = wm * 32 + (lane >> 2), cquad = lane & 3;
    #pragma unroll
    for (int mt = 0; mt < 2; ++mt)
        #pragma unroll
        for (int nt = 0; nt < 8; ++nt) {
            int col = ntile * BN + wn * 64 + nt * 8 + cquad * 2;
            float* c = acc[mt][nt];
            #pragma unroll
            for (int half = 0; half < 2; ++half) {
                int r = rbase + mt * 16 + half * 8;
                if (r < nv) {
                    int tok = s_tok[r]; float wt = s_wt[r];
                    float* orow = out + (size_t)tok * DD + col;
                    atomicAdd(orow,     wt * c[half * 2]);
                    atomicAdd(orow + 1, wt * c[half * 2 + 1]);
                }
            }
        }
}

// ---------------- launch ----------------
extern "C" void kernel_launch(void* const* d_in, const int* in_sizes, int n_in,
                              void* d_out, int out_size) {
    const float* x  = (const float*)d_in[0];
    const float* wr = (const float*)d_in[1];
    const float* Wg = (const float*)d_in[2];
    const float* Wu = (const float*)d_in[3];
    const float* Wd = (const float*)d_in[4];
    const float* sg = (const float*)d_in[5];
    const float* su = (const float*)d_in[6];
    const float* sd = (const float*)d_in[7];
    float* out = (float*)d_out;

    cudaFuncSetAttribute(gemm1_kernel, cudaFuncAttributeMaxDynamicSharedMemorySize, SMEM_DYN);
    cudaFuncSetAttribute(gemm2_kernel, cudaFuncAttributeMaxDynamicSharedMemorySize, SMEM_DYN);

    int n4 = out_size / 4;
    zero_kernel<<<(n4 + 255) / 256, 256>>>((float4*)out, n4);
    conv_x_kernel<<<T_TOK, 256>>>(x);
    conv_wgu_kernel<<<NEXP * 4096, 256>>>(Wg, Wu, sg, su);
    conv_wd_kernel<<<NEXP * DD, 512>>>(Wd, sd);
    router_kernel<<<T_TOK, 256>>>(x, wr);

    dim3 g1(32, 32, NEXP);   // N-tiles(4096/128), M-tiles(4096/128), experts
    gemm1_kernel<<<g1, 256, SMEM_DYN>>>();

    dim3 g2(8, 32, NEXP);    // N-tiles(1024/128)
    gemm2_kernel<<<g2, 256, SMEM_DYN>>>(out);
}

// round 5
// speedup vs baseline: 3.2021x; 1.0418x over previous
#include <cuda_runtime.h>
#include <cuda_fp16.h>
#include <cstdint>
#include <math.h>

// ---------------- problem constants ----------------
#define T_TOK 4096
#define DD    1024
#define HH    2048
#define EE    8
#define CAP   4096
#define NEXP  9          // 8 routed + shared as "expert 8"

// ---------------- tile config ----------------
#define BM 128
#define BN 128
#define BK 64            // k halfs per chunk (128B rows -> SW128)
#define NSTAGE 3
#define S_B   16384      // B plane offset inside a stage
#define STG   32768      // stage bytes: A 16KB + B 16KB
#define SMEM_DYN (NSTAGE * STG)   // 98304

typedef unsigned int u32;
typedef unsigned long long u64;

// ---------------- device scratch ----------------
__device__ int   g_cnt[EE];
__device__ int   g_tok[EE * CAP];
__device__ float g_wt [EE * CAP];
__device__ __half g_xh [(size_t)T_TOK * DD];
__device__ __half g_wgu[(size_t)NEXP * 4096 * DD];   // interleaved gate/up rows
__device__ __half g_wd [(size_t)NEXP * DD * HH];
__device__ __half g_hh [(size_t)NEXP * CAP * HH];

// ---------------- helpers ----------------
__device__ __forceinline__ u32 smem_u32(const void* p) {
    u32 a; asm("{ .reg .u64 t; cvta.to.shared.u64 t, %1; cvt.u32.u64 %0, t; }" : "=r"(a) : "l"(p));
    return a;
}
__device__ __forceinline__ void cpa16(u32 dst, const void* gsrc) {
    asm volatile("cp.async.cg.shared.global [%0], [%1], 16;" :: "r"(dst), "l"(gsrc) : "memory");
}
#define CP_COMMIT() asm volatile("cp.async.commit_group;" ::: "memory")
#define CP_WAIT(n)  asm volatile("cp.async.wait_group %0;" :: "n"(n) : "memory")

__device__ __forceinline__ void ldsm4(u32* r, u32 addr) {
    asm volatile("ldmatrix.sync.aligned.m8n8.x4.shared.b16 {%0,%1,%2,%3}, [%4];"
        : "=r"(r[0]), "=r"(r[1]), "=r"(r[2]), "=r"(r[3]) : "r"(addr));
}
__device__ __forceinline__ void mma16816(float* c, const u32* a, u32 b0, u32 b1) {
    asm volatile("mma.sync.aligned.m16n8k16.row.col.f32.f16.f16.f32 "
        "{%0,%1,%2,%3}, {%4,%5,%6,%7}, {%8,%9}, {%0,%1,%2,%3};"
        : "+f"(c[0]), "+f"(c[1]), "+f"(c[2]), "+f"(c[3])
        : "r"(a[0]), "r"(a[1]), "r"(a[2]), "r"(a[3]), "r"(b0), "r"(b1));
}
__device__ __forceinline__ uint2 pack_hi(float4 v) {
    __half2 h0 = __floats2half2_rn(v.x, v.y);
    __half2 h1 = __floats2half2_rn(v.z, v.w);
    uint2 r; r.x = *(u32*)&h0; r.y = *(u32*)&h1; return r;
}

// ---------------- kernel 0: zero output + counters ----------------
__global__ void zero_kernel(float4* out4, int n4) {
    int i = blockIdx.x * blockDim.x + threadIdx.x;
    if (i < n4) out4[i] = make_float4(0.f, 0.f, 0.f, 0.f);
    if (blockIdx.x == 0 && threadIdx.x < EE) g_cnt[threadIdx.x] = 0;
}

// ---------------- conversion kernels ----------------
__global__ void conv_x_kernel(const float* __restrict__ x) {
    int t = blockIdx.x, c = threadIdx.x;               // 256 thr = DD/4
    float4 v = ((const float4*)(x + (size_t)t * DD))[c];
    ((uint2*)g_xh)[(size_t)t * 256 + c] = pack_hi(v);
}
__global__ void conv_wgu_kernel(const float* __restrict__ Wg, const float* __restrict__ Wu,
                                const float* __restrict__ sg, const float* __restrict__ su) {
    int b = blockIdx.x;                                 // row in [0, NEXP*4096)
    int e = b >> 12, r = b & 4095;
    const float* src;
    if (e < EE) src = ((r & 1) ? Wu : Wg) + ((size_t)e * HH + (size_t)(r >> 1)) * DD;
    else        src = ((r & 1) ? su : sg) + (size_t)(r >> 1) * DD;
    float4 v = ((const float4*)src)[threadIdx.x];
    ((uint2*)g_wgu)[(size_t)b * 256 + threadIdx.x] = pack_hi(v);
}
__global__ void conv_wd_kernel(const float* __restrict__ Wd, const float* __restrict__ sd) {
    int b = blockIdx.x;                                 // row in [0, NEXP*DD), 512 thr
    int e = b >> 10, d = b & 1023;
    const float* src = (e < EE) ? Wd + ((size_t)e * DD + (size_t)d) * HH
                                : sd + (size_t)d * HH;
    float4 v = ((const float4*)src)[threadIdx.x];
    ((uint2*)g_wd)[(size_t)b * 512 + threadIdx.x] = pack_hi(v);
}

// ---------------- router ----------------
__global__ void router_kernel(const float* __restrict__ x,
                              const float* __restrict__ wr) {
    int t = blockIdx.x, w = threadIdx.x >> 5, lane = threadIdx.x & 31;
    const float* xr = x + (size_t)t * DD;
    const float* wrow = wr + (size_t)w * DD;
    float s = 0.f;
    for (int d = lane; d < DD; d += 32) s += xr[d] * wrow[d];
    #pragma unroll
    for (int o = 16; o; o >>= 1) s += __shfl_xor_sync(0xffffffffu, s, o);
    __shared__ float lg[EE];
    if (lane == 0) lg[w] = s;
    __syncthreads();
    if (threadIdx.x == 0) {
        int i0 = 0; float m0 = lg[0];
        #pragma unroll
        for (int j = 1; j < EE; ++j) if (lg[j] > m0) { m0 = lg[j]; i0 = j; }
        int i1 = -1; float m1 = -INFINITY;
        #pragma unroll
        for (int j = 0; j < EE; ++j) if (j != i0 && lg[j] > m1) { m1 = lg[j]; i1 = j; }
        float w0 = 1.f / (1.f + expf(m1 - m0));
        float w1 = 1.f - w0;
        int p0 = atomicAdd(&g_cnt[i0], 1);
        g_tok[i0 * CAP + p0] = t; g_wt[i0 * CAP + p0] = w0;
        int p1 = atomicAdd(&g_cnt[i1], 1);
        g_tok[i1 * CAP + p1] = t; g_wt[i1 * CAP + p1] = w1;
    }
}

// ---------------- shared GEMM machinery ----------------
// producer: thread t -> one row (A if t<128 else B), 8x 16B cp.async per chunk.
// SW128 swizzle on 128B rows: dst = (row*128 + q*16) ^ ((row&7)<<4)
#define PROD_SETUP() \
    int prow = tid & 127; \
    u32 pd[8]; \
    { \
        u32 plane = (tid >= 128) ? S_B : 0; \
        u32 psw = (u32)((prow & 7) << 4); \
        _Pragma("unroll") \
        for (int q = 0; q < 8; ++q) \
            pd[q] = plane + (((u32)(prow << 7) + (u32)(q << 4)) ^ psw); \
    }

#define ISSUE(s) do { \
    u32 _st = sb + (u32)((s) % NSTAGE) * STG; \
    const __half* _src = gsrc + (size_t)(s) * BK; \
    _Pragma("unroll") \
    for (int q = 0; q < 8; ++q) cpa16(_st + pd[q], _src + q * 8); \
} while (0)

#define FRAG_SETUP() \
    int wm = wid & 3, wn = wid >> 2; \
    int lr = lane & 15, lkb = lane >> 4; \
    u32 fsw = (u32)((lr & 7) << 4); \
    u32 baseA[2], baseB[4]; \
    _Pragma("unroll") \
    for (int tm = 0; tm < 2; ++tm) \
        baseA[tm] = (u32)((wm * 32 + tm * 16 + lr) * 128 + lkb * 16); \
    _Pragma("unroll") \
    for (int nb = 0; nb < 4; ++nb) \
        baseB[nb] = (u32)(S_B + (wn * 64 + nb * 16 + lr) * 128 + lkb * 16); \
    float acc[2][8][4]; \
    _Pragma("unroll") \
    for (int a_ = 0; a_ < 2; ++a_) \
        _Pragma("unroll") \
        for (int b_ = 0; b_ < 8; ++b_) \
            _Pragma("unroll") \
            for (int c_ = 0; c_ < 4; ++c_) acc[a_][b_][c_] = 0.f;

#define CONSUME(cur) \
    _Pragma("unroll") \
    for (int ks = 0; ks < 4; ++ks) { \
        u32 af[2][4], bf[4][4]; \
        _Pragma("unroll") \
        for (int tm = 0; tm < 2; ++tm) \
            ldsm4(af[tm], (cur) + ((baseA[tm] + ks * 32) ^ fsw)); \
        _Pragma("unroll") \
        for (int nb = 0; nb < 4; ++nb) \
            ldsm4(bf[nb], (cur) + ((baseB[nb] + ks * 32) ^ fsw)); \
        _Pragma("unroll") \
        for (int mt = 0; mt < 2; ++mt) \
            _Pragma("unroll") \
            for (int nb = 0; nb < 4; ++nb) { \
                mma16816(acc[mt][nb * 2],     af[mt], bf[nb][0], bf[nb][2]); \
                mma16816(acc[mt][nb * 2 + 1], af[mt], bf[nb][1], bf[nb][3]); \
            } \
    }

#define MAINLOOP(NC) \
    ISSUE(0); CP_COMMIT(); \
    ISSUE(1); CP_COMMIT(); \
    for (int kt = 0; kt < (NC); ++kt) { \
        CP_WAIT(1); \
        __syncthreads(); \
        if (kt + 2 < (NC)) ISSUE(kt + 2); \
        CP_COMMIT(); \
        u32 cur = sb + (u32)(kt % NSTAGE) * STG; \
        CONSUME(cur); \
    }

// =====================================================================
// GEMM1: C[128,128] = Xg[128,1024] . Wgu^T ; epilogue SwiGLU -> g_hh
// =====================================================================
__global__ void __launch_bounds__(256, 2)
gemm1_kernel() {
    int e = blockIdx.z;
    int ne = (e == EE) ? T_TOK : g_cnt[e];
    int mbase = blockIdx.y * BM;
    if (mbase >= ne) return;
    int ntile = blockIdx.x;

    extern __shared__ char smem[];
    u32 sb = smem_u32(smem);
    __shared__ int s_tok[128];
    int tid = threadIdx.x, wid = tid >> 5, lane = tid & 31;
    if (tid < 128) {
        int r = mbase + tid;
        s_tok[tid] = (e == EE) ? r : ((r < ne) ? g_tok[e * CAP + r] : g_tok[e * CAP]);
    }
    __syncthreads();

    PROD_SETUP();
    const __half* gsrc;
    if (tid < 128) gsrc = g_xh + (size_t)s_tok[prow] * DD;
    else           gsrc = g_wgu + (size_t)(e * 4096 + ntile * 128 + prow) * DD;

    FRAG_SETUP();
    MAINLOOP(DD / BK);   // 16 chunks

    // epilogue: SwiGLU -> fp16 h
    size_t slotBase = (size_t)e * CAP + mbase;
    int rbase = wm * 32 + (lane >> 2), cquad = lane & 3;
    #pragma unroll
    for (int mt = 0; mt < 2; ++mt)
        #pragma unroll
        for (int nt = 0; nt < 8; ++nt) {
            int hcol = ntile * 64 + wn * 32 + nt * 4 + cquad;
            float* c = acc[mt][nt];
            #pragma unroll
            for (int half = 0; half < 2; ++half) {
                int r = rbase + mt * 16 + half * 8;
                float gv = c[half * 2], uv = c[half * 2 + 1];
                float h = (gv / (1.f + __expf(-gv))) * uv;
                g_hh[(slotBase + (size_t)r) * HH + (size_t)hcol] = __float2half_rn(h);
            }
        }
}

// =====================================================================
// GEMM2: C[128,128] = h[128,2048] . Wd^T ; split-K=2; atomic scatter
// =====================================================================
__global__ void __launch_bounds__(256, 2)
gemm2_kernel(float* __restrict__ out) {
    int z = blockIdx.z;
    int e = z >> 1, kh = z & 1;
    int ne = (e == EE) ? T_TOK : g_cnt[e];
    int mbase = blockIdx.y * BM;
    if (mbase >= ne) return;
    int ntile = blockIdx.x;

    extern __shared__ char smem[];
    u32 sb = smem_u32(smem);
    __shared__ int   s_tok[128];
    __shared__ float s_wt[128];
    int tid = threadIdx.x, wid = tid >> 5, lane = tid & 31;
    if (tid < 128) {
        int r = mbase + tid;
        if (e == EE)     { s_tok[tid] = r; s_wt[tid] = 1.f; }
        else if (r < ne) { s_tok[tid] = g_tok[e * CAP + r]; s_wt[tid] = g_wt[e * CAP + r]; }
        else             { s_tok[tid] = 0; s_wt[tid] = 0.f; }
    }
    __syncthreads();

    size_t slotBase = (size_t)e * CAP + mbase;
    size_t koff = (size_t)kh * (HH / 2);

    PROD_SETUP();
    const __half* gsrc;
    if (tid < 128) gsrc = g_hh + (slotBase + (size_t)prow) * HH + koff;
    else           gsrc = g_wd + (size_t)(e * DD + ntile * 128 + prow) * HH + koff;

    FRAG_SETUP();
    MAINLOOP((HH / 2) / BK);  // 16 chunks per split half

    // epilogue: weighted atomic scatter
    int nv = ne - mbase; if (nv > BM) nv = BM;
    int rbase = wm * 32 + (lane >> 2), cquad = lane & 3;
    #pragma unroll
    for (int mt = 0; mt < 2; ++mt)
        #pragma unroll
        for (int nt = 0; nt < 8; ++nt) {
            int col = ntile * BN + wn * 64 + nt * 8 + cquad * 2;
            float* c = acc[mt][nt];
            #pragma unroll
            for (int half = 0; half < 2; ++half) {
                int r = rbase + mt * 16 + half * 8;
                if (r < nv) {
                    int tok = s_tok[r]; float wt = s_wt[r];
                    float* orow = out + (size_t)tok * DD + col;
                    atomicAdd(orow,     wt * c[half * 2]);
                    atomicAdd(orow + 1, wt * c[half * 2 + 1]);
                }
            }
        }
}

// ---------------- launch ----------------
extern "C" void kernel_launch(void* const* d_in, const int* in_sizes, int n_in,
                              void* d_out, int out_size) {
    const float* x  = (const float*)d_in[0];
    const float* wr = (const float*)d_in[1];
    const float* Wg = (const float*)d_in[2];
    const float* Wu = (const float*)d_in[3];
    const float* Wd = (const float*)d_in[4];
    const float* sg = (const float*)d_in[5];
    const float* su = (const float*)d_in[6];
    const float* sd = (const float*)d_in[7];
    float* out = (float*)d_out;

    cudaFuncSetAttribute(gemm1_kernel, cudaFuncAttributeMaxDynamicSharedMemorySize, SMEM_DYN);
    cudaFuncSetAttribute(gemm2_kernel, cudaFuncAttributeMaxDynamicSharedMemorySize, SMEM_DYN);

    int n4 = out_size / 4;
    zero_kernel<<<(n4 + 255) / 256, 256>>>((float4*)out, n4);
    conv_x_kernel<<<T_TOK, 256>>>(x);
    conv_wgu_kernel<<<NEXP * 4096, 256>>>(Wg, Wu, sg, su);
    conv_wd_kernel<<<NEXP * DD, 512>>>(Wd, sd);
    router_kernel<<<T_TOK, 256>>>(x, wr);

    dim3 g1(32, 32, NEXP);       // N-tiles(4096/128), M-tiles(4096/128), experts
    gemm1_kernel<<<g1, 256, SMEM_DYN>>>();

    dim3 g2(8, 32, NEXP * 2);    // N-tiles(1024/128), M-tiles, experts x split-K
    gemm2_kernel<<<g2, 256, SMEM_DYN>>>(out);
}